// round 1
// baseline (speedup 1.0000x reference)
#include <cuda_runtime.h>

#define B   4
#define SQ  2048
#define SKk 2048
#define DD  512
#define H   8
#define HD  64
#define SCALE 0.125f
#define EPSLN 1e-5f

#define NTOK (B*SQ)          // 8192
#define LINSZ (B*SQ*DD)      // 4194304

// Scratch (device globals: allocation-free rule)
__device__ float g_qlin[LINSZ];
__device__ float g_klin[LINSZ];
__device__ float g_vlin[LINSZ];
__device__ float g_ctx[LINSZ];
__device__ float g_oproj[LINSZ];

// ---------------------------------------------------------------------------
// Generic Y = X @ W^T + bias   (X: [M,K] row-major, W: [N,K] row-major)
// BM=BN=64, BK=32, 256 threads, 4x4 per thread.
// ---------------------------------------------------------------------------
__global__ __launch_bounds__(256) void linear_kernel(
    const float* __restrict__ X, const float* __restrict__ W,
    const float* __restrict__ bias, float* __restrict__ Y,
    int M, int N, int K)
{
    __shared__ float Xs[32][68];
    __shared__ float Ws[32][68];
    const int tid = threadIdx.x;
    const int tx = tid & 15;        // 0..15 -> n
    const int ty = tid >> 4;        // 0..15 -> m
    const int m0 = blockIdx.y * 64;
    const int n0 = blockIdx.x * 64;

    float acc[4][4] = {};

    for (int k0 = 0; k0 < K; k0 += 32) {
        #pragma unroll
        for (int i = 0; i < 2; i++) {
            int f   = tid + i * 256;        // 0..511 float4 slots
            int row = f >> 3;               // 0..63
            int kq  = f & 7;                // 0..7
            float4 xv = *(const float4*)(X + (size_t)(m0 + row) * K + k0 + kq * 4);
            Xs[kq*4+0][row] = xv.x; Xs[kq*4+1][row] = xv.y;
            Xs[kq*4+2][row] = xv.z; Xs[kq*4+3][row] = xv.w;
            float4 wv = *(const float4*)(W + (size_t)(n0 + row) * K + k0 + kq * 4);
            Ws[kq*4+0][row] = wv.x; Ws[kq*4+1][row] = wv.y;
            Ws[kq*4+2][row] = wv.z; Ws[kq*4+3][row] = wv.w;
        }
        __syncthreads();
        #pragma unroll
        for (int kk = 0; kk < 32; kk++) {
            float4 a = *(const float4*)&Xs[kk][ty * 4];
            float4 b = *(const float4*)&Ws[kk][tx * 4];
            float ar[4] = {a.x, a.y, a.z, a.w};
            float br[4] = {b.x, b.y, b.z, b.w};
            #pragma unroll
            for (int i = 0; i < 4; i++)
                #pragma unroll
                for (int j = 0; j < 4; j++)
                    acc[i][j] += ar[i] * br[j];
        }
        __syncthreads();
    }

    float4 bv = *(const float4*)(bias + n0 + tx * 4);
    #pragma unroll
    for (int i = 0; i < 4; i++) {
        float4 r;
        r.x = acc[i][0] + bv.x; r.y = acc[i][1] + bv.y;
        r.z = acc[i][2] + bv.z; r.w = acc[i][3] + bv.w;
        *(float4*)(Y + (size_t)(m0 + ty * 4 + i) * N + n0 + tx * 4) = r;
    }
}

// ---------------------------------------------------------------------------
// scores[b,h,q,k] = SCALE * dot64(qh[b,q,h,:], kh[b,k,h,:])
// K=64 fully resident in smem. Writes raw scaled scores to attn region.
// ---------------------------------------------------------------------------
__global__ __launch_bounds__(256) void scores_kernel(float* __restrict__ attn)
{
    __shared__ float Qs[64][68];
    __shared__ float Ks[64][68];
    const int tid = threadIdx.x;
    const int tx = tid & 15;
    const int ty = tid >> 4;
    const int bh = blockIdx.z;
    const int b  = bh >> 3;
    const int h  = bh & 7;
    const int m0 = blockIdx.y * 64;
    const int n0 = blockIdx.x * 64;

    const float* qbase = g_qlin + (size_t)b * SQ * DD + h * HD;
    const float* kbase = g_klin + (size_t)b * SKk * DD + h * HD;

    #pragma unroll
    for (int i = 0; i < 4; i++) {
        int f   = tid + i * 256;    // 0..1023
        int row = f >> 4;           // 0..63
        int kq  = f & 15;           // 0..15
        float4 qv = *(const float4*)(qbase + (size_t)(m0 + row) * DD + kq * 4);
        Qs[kq*4+0][row] = qv.x; Qs[kq*4+1][row] = qv.y;
        Qs[kq*4+2][row] = qv.z; Qs[kq*4+3][row] = qv.w;
        float4 kv = *(const float4*)(kbase + (size_t)(n0 + row) * DD + kq * 4);
        Ks[kq*4+0][row] = kv.x; Ks[kq*4+1][row] = kv.y;
        Ks[kq*4+2][row] = kv.z; Ks[kq*4+3][row] = kv.w;
    }
    __syncthreads();

    float acc[4][4] = {};
    #pragma unroll
    for (int kk = 0; kk < 64; kk++) {
        float4 a = *(const float4*)&Qs[kk][ty * 4];
        float4 bq = *(const float4*)&Ks[kk][tx * 4];
        float ar[4] = {a.x, a.y, a.z, a.w};
        float br[4] = {bq.x, bq.y, bq.z, bq.w};
        #pragma unroll
        for (int i = 0; i < 4; i++)
            #pragma unroll
            for (int j = 0; j < 4; j++)
                acc[i][j] += ar[i] * br[j];
    }

    float* obase = attn + (size_t)bh * SQ * SKk;
    #pragma unroll
    for (int i = 0; i < 4; i++) {
        float4 r;
        r.x = acc[i][0] * SCALE; r.y = acc[i][1] * SCALE;
        r.z = acc[i][2] * SCALE; r.w = acc[i][3] * SCALE;
        *(float4*)(obase + (size_t)(m0 + ty * 4 + i) * SKk + n0 + tx * 4) = r;
    }
}

// ---------------------------------------------------------------------------
// In-place row softmax over SK=2048. One block per row, 256 threads, 8 el/thr.
// ---------------------------------------------------------------------------
__global__ __launch_bounds__(256) void softmax_kernel(float* __restrict__ attn)
{
    __shared__ float sbuf[8];
    const size_t row = blockIdx.x;
    float* p = attn + row * (size_t)SKk;
    const int tid = threadIdx.x;
    const int lane = tid & 31;
    const int warp = tid >> 5;

    float4 v0 = ((const float4*)p)[tid];
    float4 v1 = ((const float4*)p)[tid + 256];

    float mx = fmaxf(fmaxf(fmaxf(v0.x, v0.y), fmaxf(v0.z, v0.w)),
                     fmaxf(fmaxf(v1.x, v1.y), fmaxf(v1.z, v1.w)));
    #pragma unroll
    for (int o = 16; o; o >>= 1) mx = fmaxf(mx, __shfl_xor_sync(~0u, mx, o));
    if (lane == 0) sbuf[warp] = mx;
    __syncthreads();
    mx = sbuf[0];
    #pragma unroll
    for (int i = 1; i < 8; i++) mx = fmaxf(mx, sbuf[i]);
    __syncthreads();

    v0.x = expf(v0.x - mx); v0.y = expf(v0.y - mx);
    v0.z = expf(v0.z - mx); v0.w = expf(v0.w - mx);
    v1.x = expf(v1.x - mx); v1.y = expf(v1.y - mx);
    v1.z = expf(v1.z - mx); v1.w = expf(v1.w - mx);

    float s = v0.x + v0.y + v0.z + v0.w + v1.x + v1.y + v1.z + v1.w;
    #pragma unroll
    for (int o = 16; o; o >>= 1) s += __shfl_xor_sync(~0u, s, o);
    if (lane == 0) sbuf[warp] = s;
    __syncthreads();
    s = sbuf[0];
    #pragma unroll
    for (int i = 1; i < 8; i++) s += sbuf[i];

    float inv = 1.0f / s;
    v0.x *= inv; v0.y *= inv; v0.z *= inv; v0.w *= inv;
    v1.x *= inv; v1.y *= inv; v1.z *= inv; v1.w *= inv;
    ((float4*)p)[tid] = v0;
    ((float4*)p)[tid + 256] = v1;
}

// ---------------------------------------------------------------------------
// ctx[b,q,h,:] = attn[b,h,q,:] @ vh[b,:,h,:]    (M=2048, N=64, K=2048 per bh)
// ---------------------------------------------------------------------------
__global__ __launch_bounds__(256) void pv_kernel(const float* __restrict__ attn)
{
    __shared__ float Ps[32][68];
    __shared__ float Vs[32][64];
    const int tid = threadIdx.x;
    const int tx = tid & 15;
    const int ty = tid >> 4;
    const int bh = blockIdx.y;
    const int b  = bh >> 3;
    const int h  = bh & 7;
    const int m0 = blockIdx.x * 64;

    const float* pbase = attn + (size_t)bh * SQ * SKk;
    const float* vbase = g_vlin + (size_t)b * SKk * DD + h * HD;

    float acc[4][4] = {};

    for (int k0 = 0; k0 < SKk; k0 += 32) {
        #pragma unroll
        for (int i = 0; i < 2; i++) {
            int f = tid + i * 256;          // 0..511
            {   // P tile: 64 rows x 32 cols
                int row = f >> 3;           // 0..63
                int kq  = f & 7;            // 0..7
                float4 pv = *(const float4*)(pbase + (size_t)(m0 + row) * SKk + k0 + kq * 4);
                Ps[kq*4+0][row] = pv.x; Ps[kq*4+1][row] = pv.y;
                Ps[kq*4+2][row] = pv.z; Ps[kq*4+3][row] = pv.w;
            }
            {   // V tile: 32 rows x 64 cols, direct layout
                int row = f >> 4;           // 0..31
                int kq  = f & 15;           // 0..15
                float4 vv = *(const float4*)(vbase + (size_t)(k0 + row) * DD + kq * 4);
                *(float4*)&Vs[row][kq * 4] = vv;
            }
        }
        __syncthreads();
        #pragma unroll
        for (int kk = 0; kk < 32; kk++) {
            float4 a = *(const float4*)&Ps[kk][ty * 4];
            float4 bb = *(const float4*)&Vs[kk][tx * 4];
            float ar[4] = {a.x, a.y, a.z, a.w};
            float br[4] = {bb.x, bb.y, bb.z, bb.w};
            #pragma unroll
            for (int i = 0; i < 4; i++)
                #pragma unroll
                for (int j = 0; j < 4; j++)
                    acc[i][j] += ar[i] * br[j];
        }
        __syncthreads();
    }

    #pragma unroll
    for (int i = 0; i < 4; i++) {
        float4 r;
        r.x = acc[i][0]; r.y = acc[i][1]; r.z = acc[i][2]; r.w = acc[i][3];
        *(float4*)(g_ctx + (size_t)(b * SQ + m0 + ty * 4 + i) * DD + h * HD + tx * 4) = r;
    }
}

// ---------------------------------------------------------------------------
// out = LayerNorm(q_lin + oproj) * g + b     one block per row (512 elems)
// ---------------------------------------------------------------------------
__global__ __launch_bounds__(128) void ln_kernel(
    const float* __restrict__ gamma, const float* __restrict__ beta,
    float* __restrict__ out)
{
    __shared__ float sbuf[4];
    const size_t row = blockIdx.x;
    const int tid = threadIdx.x;
    const int lane = tid & 31;
    const int warp = tid >> 5;

    float4 a = ((const float4*)(g_qlin + row * DD))[tid];
    float4 c = ((const float4*)(g_oproj + row * DD))[tid];
    float4 x;
    x.x = a.x + c.x; x.y = a.y + c.y; x.z = a.z + c.z; x.w = a.w + c.w;

    float s = x.x + x.y + x.z + x.w;
    #pragma unroll
    for (int o = 16; o; o >>= 1) s += __shfl_xor_sync(~0u, s, o);
    if (lane == 0) sbuf[warp] = s;
    __syncthreads();
    s = sbuf[0] + sbuf[1] + sbuf[2] + sbuf[3];
    float mu = s * (1.0f / DD);
    __syncthreads();

    float dx = x.x - mu, dy = x.y - mu, dz = x.z - mu, dw = x.w - mu;
    float v = dx * dx + dy * dy + dz * dz + dw * dw;
    #pragma unroll
    for (int o = 16; o; o >>= 1) v += __shfl_xor_sync(~0u, v, o);
    if (lane == 0) sbuf[warp] = v;
    __syncthreads();
    v = sbuf[0] + sbuf[1] + sbuf[2] + sbuf[3];
    float rstd = rsqrtf(v * (1.0f / DD) + EPSLN);

    float4 g4 = ((const float4*)gamma)[tid];
    float4 b4 = ((const float4*)beta)[tid];
    float4 y;
    y.x = dx * rstd * g4.x + b4.x;
    y.y = dy * rstd * g4.y + b4.y;
    y.z = dz * rstd * g4.z + b4.z;
    y.w = dw * rstd * g4.w + b4.w;
    ((float4*)(out + row * DD))[tid] = y;
}

// ---------------------------------------------------------------------------
extern "C" void kernel_launch(void* const* d_in, const int* in_sizes, int n_in,
                              void* d_out, int out_size)
{
    const float* q    = (const float*)d_in[0];
    const float* k    = (const float*)d_in[1];
    const float* v    = (const float*)d_in[2];
    const float* Wq   = (const float*)d_in[3];
    const float* bq   = (const float*)d_in[4];
    const float* Wk   = (const float*)d_in[5];
    const float* bk   = (const float*)d_in[6];
    const float* Wv   = (const float*)d_in[7];
    const float* bv   = (const float*)d_in[8];
    const float* Wo   = (const float*)d_in[9];
    const float* bo   = (const float*)d_in[10];
    const float* ln_g = (const float*)d_in[11];
    const float* ln_b = (const float*)d_in[12];

    float* out  = (float*)d_out;
    float* attn = out + (size_t)LINSZ;   // [B,H,SQ,SK] after [B,SQ,D]

    float *qlin, *klin, *vlin, *ctx, *oproj;
    cudaGetSymbolAddress((void**)&qlin,  g_qlin);
    cudaGetSymbolAddress((void**)&klin,  g_klin);
    cudaGetSymbolAddress((void**)&vlin,  g_vlin);
    cudaGetSymbolAddress((void**)&ctx,   g_ctx);
    cudaGetSymbolAddress((void**)&oproj, g_oproj);

    dim3 blk(256);
    dim3 gl(DD / 64, NTOK / 64);   // (8, 128)

    linear_kernel<<<gl, blk>>>(q, Wq, bq, qlin, NTOK, DD, DD);
    linear_kernel<<<gl, blk>>>(k, Wk, bk, klin, NTOK, DD, DD);
    linear_kernel<<<gl, blk>>>(v, Wv, bv, vlin, NTOK, DD, DD);

    scores_kernel<<<dim3(SKk / 64, SQ / 64, B * H), blk>>>(attn);
    softmax_kernel<<<B * H * SQ, 256>>>(attn);
    pv_kernel<<<dim3(SQ / 64, B * H), blk>>>(attn);

    linear_kernel<<<gl, blk>>>(ctx, Wo, bo, oproj, NTOK, DD, DD);
    ln_kernel<<<NTOK, 128>>>(ln_g, ln_b, out);
}

// round 2
// speedup vs baseline: 2.5120x; 2.5120x over previous
#include <cuda_runtime.h>
#include <cuda_bf16.h>
#include <cstdint>

#define B_  4
#define SQ  2048
#define SK_ 2048
#define DD  512
#define H_  8
#define HD  64
#define SCALE 0.125f
#define EPSLN 1e-5f

#define NTOK (B_*SQ)            // 8192
#define LINSZ (NTOK*DD)         // 4194304

// Scratch (device globals: allocation-free rule)
__device__ float g_qlin[LINSZ];
__device__ float g_klin[LINSZ];
__device__ float g_vlin[LINSZ];
__device__ float g_ctx[LINSZ];
__device__ float g_oproj[LINSZ];

// ---------------------------------------------------------------------------
// Helpers: split-bf16 (x = hi + lo), packed pairs for smem staging
// ---------------------------------------------------------------------------
__device__ __forceinline__ void split2(float x, float y, uint32_t& hi, uint32_t& lo) {
    __nv_bfloat16 hx = __float2bfloat16(x), hy = __float2bfloat16(y);
    float rx = x - __bfloat162float(hx);
    float ry = y - __bfloat162float(hy);
    __nv_bfloat16 lx = __float2bfloat16(rx), ly = __float2bfloat16(ry);
    hi = ((uint32_t)__bfloat16_as_ushort(hy) << 16) | __bfloat16_as_ushort(hx);
    lo = ((uint32_t)__bfloat16_as_ushort(ly) << 16) | __bfloat16_as_ushort(lx);
}

__device__ __forceinline__ void split1(float x, __nv_bfloat16& h, __nv_bfloat16& l) {
    h = __float2bfloat16(x);
    l = __float2bfloat16(x - __bfloat162float(h));
}

__device__ __forceinline__ void mma16816(float* c, const uint32_t* a, const uint32_t* b) {
    asm volatile(
        "mma.sync.aligned.m16n8k16.row.col.f32.bf16.bf16.f32 "
        "{%0,%1,%2,%3},{%4,%5,%6,%7},{%8,%9},{%0,%1,%2,%3};\n"
        : "+f"(c[0]), "+f"(c[1]), "+f"(c[2]), "+f"(c[3])
        : "r"(a[0]), "r"(a[1]), "r"(a[2]), "r"(a[3]), "r"(b[0]), "r"(b[1]));
}

// ---------------------------------------------------------------------------
// Generic 128x128 block GEMM core:  C = scale * (A @ B^T) + bias
// A: rows of M at stride lda (fp32), B: rows of N at stride ldb (fp32).
// 256 threads = 8 warps (2 x 4), warp tile 64x32, BK=32.
// Split-bf16: 3 MMAs per fragment pair for ~fp32 accuracy.
// smem row stride = 36 bf16 elems (bank-conflict-free fragment loads).
// ---------------------------------------------------------------------------
__device__ __forceinline__ void gemm128x128(
    const float* __restrict__ A, int lda,
    const float* __restrict__ Bm, int ldb,
    float* __restrict__ C, long long ldc,
    int K, const float* __restrict__ bias, float scale,
    __nv_bfloat16* sAh, __nv_bfloat16* sAl,
    __nv_bfloat16* sBh, __nv_bfloat16* sBl)
{
    const int tid  = threadIdx.x;
    const int wid  = tid >> 5, lane = tid & 31;
    const int wm   = wid >> 2;          // 0..1  (64 rows)
    const int wn   = wid & 3;           // 0..3  (32 cols)
    const int grp  = lane >> 2;         // 0..7
    const int tig  = lane & 3;          // 0..3

    float acc[4][4][4] = {};

    for (int k0 = 0; k0 < K; k0 += 32) {
        // ---- stage A and B tiles: 128x32 fp32 each -> hi/lo bf16 smem ----
        #pragma unroll
        for (int i = 0; i < 4; i++) {
            int s   = tid + i * 256;    // 0..1023 float4 slots
            int row = s >> 3;
            int c   = s & 7;
            float4 av = *(const float4*)(A + (size_t)row * lda + k0 + c * 4);
            uint32_t h0, l0, h1, l1;
            split2(av.x, av.y, h0, l0);
            split2(av.z, av.w, h1, l1);
            uint32_t* ph = (uint32_t*)(sAh + row * 36 + c * 4);
            uint32_t* pl = (uint32_t*)(sAl + row * 36 + c * 4);
            ph[0] = h0; ph[1] = h1;
            pl[0] = l0; pl[1] = l1;

            float4 bv = *(const float4*)(Bm + (size_t)row * ldb + k0 + c * 4);
            split2(bv.x, bv.y, h0, l0);
            split2(bv.z, bv.w, h1, l1);
            ph = (uint32_t*)(sBh + row * 36 + c * 4);
            pl = (uint32_t*)(sBl + row * 36 + c * 4);
            ph[0] = h0; ph[1] = h1;
            pl[0] = l0; pl[1] = l1;
        }
        __syncthreads();

        #pragma unroll
        for (int ks = 0; ks < 2; ks++) {
            const int kb = ks * 16 + tig * 2;
            uint32_t ah[4][4], al[4][4];
            #pragma unroll
            for (int i = 0; i < 4; i++) {
                int r0 = wm * 64 + i * 16 + grp;
                ah[i][0] = *(const uint32_t*)(sAh + r0 * 36 + kb);
                ah[i][1] = *(const uint32_t*)(sAh + (r0 + 8) * 36 + kb);
                ah[i][2] = *(const uint32_t*)(sAh + r0 * 36 + kb + 8);
                ah[i][3] = *(const uint32_t*)(sAh + (r0 + 8) * 36 + kb + 8);
                al[i][0] = *(const uint32_t*)(sAl + r0 * 36 + kb);
                al[i][1] = *(const uint32_t*)(sAl + (r0 + 8) * 36 + kb);
                al[i][2] = *(const uint32_t*)(sAl + r0 * 36 + kb + 8);
                al[i][3] = *(const uint32_t*)(sAl + (r0 + 8) * 36 + kb + 8);
            }
            uint32_t bh[4][2], bl[4][2];
            #pragma unroll
            for (int j = 0; j < 4; j++) {
                int nr = wn * 32 + j * 8 + grp;
                bh[j][0] = *(const uint32_t*)(sBh + nr * 36 + kb);
                bh[j][1] = *(const uint32_t*)(sBh + nr * 36 + kb + 8);
                bl[j][0] = *(const uint32_t*)(sBl + nr * 36 + kb);
                bl[j][1] = *(const uint32_t*)(sBl + nr * 36 + kb + 8);
            }
            #pragma unroll
            for (int i = 0; i < 4; i++)
                #pragma unroll
                for (int j = 0; j < 4; j++) {
                    mma16816(acc[i][j], ah[i], bh[j]);
                    mma16816(acc[i][j], ah[i], bl[j]);
                    mma16816(acc[i][j], al[i], bh[j]);
                }
        }
        __syncthreads();
    }

    // ---- epilogue ----
    #pragma unroll
    for (int i = 0; i < 4; i++) {
        #pragma unroll
        for (int j = 0; j < 4; j++) {
            int r  = wm * 64 + i * 16 + grp;
            int cN = wn * 32 + j * 8 + tig * 2;
            float bv0 = bias ? bias[cN]     : 0.0f;
            float bv1 = bias ? bias[cN + 1] : 0.0f;
            C[(long long)r * ldc + cN]           = acc[i][j][0] * scale + bv0;
            C[(long long)r * ldc + cN + 1]       = acc[i][j][1] * scale + bv1;
            C[(long long)(r + 8) * ldc + cN]     = acc[i][j][2] * scale + bv0;
            C[(long long)(r + 8) * ldc + cN + 1] = acc[i][j][3] * scale + bv1;
        }
    }
}

// ---------------------------------------------------------------------------
// Y = X @ W^T + bias   (M=NTOK, N=512, K=512)
// ---------------------------------------------------------------------------
__global__ __launch_bounds__(256) void linear_mma(
    const float* __restrict__ X, const float* __restrict__ W,
    const float* __restrict__ bias, float* __restrict__ Y, int K, int N)
{
    __shared__ __nv_bfloat16 sAh[128 * 36], sAl[128 * 36];
    __shared__ __nv_bfloat16 sBh[128 * 36], sBl[128 * 36];
    const int m0 = blockIdx.y * 128;
    const int n0 = blockIdx.x * 128;
    gemm128x128(X + (size_t)m0 * K, K,
                W + (size_t)n0 * K, K,
                Y + (size_t)m0 * N + n0, N,
                K, bias + n0, 1.0f, sAh, sAl, sBh, sBl);
}

// ---------------------------------------------------------------------------
// scores[b,h,q,k] = SCALE * qh . kh   (per bh: M=N=2048, K=64)
// ---------------------------------------------------------------------------
__global__ __launch_bounds__(256) void scores_mma(float* __restrict__ attn)
{
    __shared__ __nv_bfloat16 sAh[128 * 36], sAl[128 * 36];
    __shared__ __nv_bfloat16 sBh[128 * 36], sBl[128 * 36];
    const int bh = blockIdx.z;
    const int b  = bh >> 3, h = bh & 7;
    const float* A  = g_qlin + (size_t)b * SQ * DD + h * HD + (size_t)blockIdx.y * 128 * DD;
    const float* Bp = g_klin + (size_t)b * SK_ * DD + h * HD + (size_t)blockIdx.x * 128 * DD;
    float* C = attn + (size_t)bh * SQ * SK_ + (size_t)blockIdx.y * 128 * SK_ + blockIdx.x * 128;
    gemm128x128(A, DD, Bp, DD, C, SK_, HD, nullptr, SCALE, sAh, sAl, sBh, sBl);
}

// ---------------------------------------------------------------------------
// In-place row softmax over SK=2048. One block per row, 256 threads.
// ---------------------------------------------------------------------------
__global__ __launch_bounds__(256) void softmax_kernel(float* __restrict__ attn)
{
    __shared__ float sbuf[8];
    const size_t row = blockIdx.x;
    float* p = attn + row * (size_t)SK_;
    const int tid = threadIdx.x;
    const int lane = tid & 31;
    const int warp = tid >> 5;

    float4 v0 = ((const float4*)p)[tid];
    float4 v1 = ((const float4*)p)[tid + 256];

    float mx = fmaxf(fmaxf(fmaxf(v0.x, v0.y), fmaxf(v0.z, v0.w)),
                     fmaxf(fmaxf(v1.x, v1.y), fmaxf(v1.z, v1.w)));
    #pragma unroll
    for (int o = 16; o; o >>= 1) mx = fmaxf(mx, __shfl_xor_sync(~0u, mx, o));
    if (lane == 0) sbuf[warp] = mx;
    __syncthreads();
    mx = sbuf[0];
    #pragma unroll
    for (int i = 1; i < 8; i++) mx = fmaxf(mx, sbuf[i]);
    __syncthreads();

    v0.x = expf(v0.x - mx); v0.y = expf(v0.y - mx);
    v0.z = expf(v0.z - mx); v0.w = expf(v0.w - mx);
    v1.x = expf(v1.x - mx); v1.y = expf(v1.y - mx);
    v1.z = expf(v1.z - mx); v1.w = expf(v1.w - mx);

    float s = v0.x + v0.y + v0.z + v0.w + v1.x + v1.y + v1.z + v1.w;
    #pragma unroll
    for (int o = 16; o; o >>= 1) s += __shfl_xor_sync(~0u, s, o);
    if (lane == 0) sbuf[warp] = s;
    __syncthreads();
    s = sbuf[0];
    #pragma unroll
    for (int i = 1; i < 8; i++) s += sbuf[i];

    float inv = 1.0f / s;
    v0.x *= inv; v0.y *= inv; v0.z *= inv; v0.w *= inv;
    v1.x *= inv; v1.y *= inv; v1.z *= inv; v1.w *= inv;
    ((float4*)p)[tid] = v0;
    ((float4*)p)[tid + 256] = v1;
}

// ---------------------------------------------------------------------------
// ctx = P @ V   (per bh: M=2048, N=64, K=2048), split-bf16 MMA.
// 8 warps = 4 x 2, warp tile 32x32, BK=32. V staged transposed [n][k].
// ---------------------------------------------------------------------------
__global__ __launch_bounds__(256) void pv_mma(const float* __restrict__ attn)
{
    __shared__ __nv_bfloat16 sPh[128 * 36], sPl[128 * 36];
    __shared__ __nv_bfloat16 sVh[64 * 36],  sVl[64 * 36];
    const int tid  = threadIdx.x;
    const int wid  = tid >> 5, lane = tid & 31;
    const int wm   = wid >> 1;          // 0..3 (32 rows)
    const int wn   = wid & 1;           // 0..1 (32 cols)
    const int grp  = lane >> 2, tig = lane & 3;
    const int bh = blockIdx.y;
    const int b  = bh >> 3, h = bh & 7;
    const int m0 = blockIdx.x * 128;

    const float* P = attn + (size_t)bh * SQ * SK_ + (size_t)m0 * SK_;
    const float* V = g_vlin + (size_t)b * SK_ * DD + h * HD;

    float acc[2][4][4] = {};

    for (int k0 = 0; k0 < SK_; k0 += 32) {
        // stage P tile 128x32
        #pragma unroll
        for (int i = 0; i < 4; i++) {
            int s = tid + i * 256;
            int row = s >> 3, c = s & 7;
            float4 pv = *(const float4*)(P + (size_t)row * SK_ + k0 + c * 4);
            uint32_t h0, l0, h1, l1;
            split2(pv.x, pv.y, h0, l0);
            split2(pv.z, pv.w, h1, l1);
            uint32_t* ph = (uint32_t*)(sPh + row * 36 + c * 4);
            uint32_t* pl = (uint32_t*)(sPl + row * 36 + c * 4);
            ph[0] = h0; ph[1] = h1;
            pl[0] = l0; pl[1] = l1;
        }
        // stage V tile 32(k) x 64(n), transposed into [n][k]
        #pragma unroll
        for (int i = 0; i < 2; i++) {
            int s = tid + i * 256;      // 0..511
            int kr = s >> 4, c = s & 15;
            float4 vv = *(const float4*)(V + (size_t)(k0 + kr) * DD + c * 4);
            float vals[4] = {vv.x, vv.y, vv.z, vv.w};
            #pragma unroll
            for (int e = 0; e < 4; e++) {
                __nv_bfloat16 hh, ll;
                split1(vals[e], hh, ll);
                sVh[(c * 4 + e) * 36 + kr] = hh;
                sVl[(c * 4 + e) * 36 + kr] = ll;
            }
        }
        __syncthreads();

        #pragma unroll
        for (int ks = 0; ks < 2; ks++) {
            const int kb = ks * 16 + tig * 2;
            uint32_t ah[2][4], al[2][4];
            #pragma unroll
            for (int i = 0; i < 2; i++) {
                int r0 = wm * 32 + i * 16 + grp;
                ah[i][0] = *(const uint32_t*)(sPh + r0 * 36 + kb);
                ah[i][1] = *(const uint32_t*)(sPh + (r0 + 8) * 36 + kb);
                ah[i][2] = *(const uint32_t*)(sPh + r0 * 36 + kb + 8);
                ah[i][3] = *(const uint32_t*)(sPh + (r0 + 8) * 36 + kb + 8);
                al[i][0] = *(const uint32_t*)(sPl + r0 * 36 + kb);
                al[i][1] = *(const uint32_t*)(sPl + (r0 + 8) * 36 + kb);
                al[i][2] = *(const uint32_t*)(sPl + r0 * 36 + kb + 8);
                al[i][3] = *(const uint32_t*)(sPl + (r0 + 8) * 36 + kb + 8);
            }
            uint32_t bhf[4][2], blf[4][2];
            #pragma unroll
            for (int j = 0; j < 4; j++) {
                int nr = wn * 32 + j * 8 + grp;
                bhf[j][0] = *(const uint32_t*)(sVh + nr * 36 + kb);
                bhf[j][1] = *(const uint32_t*)(sVh + nr * 36 + kb + 8);
                blf[j][0] = *(const uint32_t*)(sVl + nr * 36 + kb);
                blf[j][1] = *(const uint32_t*)(sVl + nr * 36 + kb + 8);
            }
            #pragma unroll
            for (int i = 0; i < 2; i++)
                #pragma unroll
                for (int j = 0; j < 4; j++) {
                    mma16816(acc[i][j], ah[i], bhf[j]);
                    mma16816(acc[i][j], ah[i], blf[j]);
                    mma16816(acc[i][j], al[i], bhf[j]);
                }
        }
        __syncthreads();
    }

    #pragma unroll
    for (int i = 0; i < 2; i++)
        #pragma unroll
        for (int j = 0; j < 4; j++) {
            int r  = m0 + wm * 32 + i * 16 + grp;
            int cN = wn * 32 + j * 8 + tig * 2;
            float* o0 = g_ctx + (size_t)(b * SQ + r) * DD + h * HD + cN;
            float* o1 = g_ctx + (size_t)(b * SQ + r + 8) * DD + h * HD + cN;
            o0[0] = acc[i][j][0]; o0[1] = acc[i][j][1];
            o1[0] = acc[i][j][2]; o1[1] = acc[i][j][3];
        }
}

// ---------------------------------------------------------------------------
// out = LayerNorm(q_lin + oproj) * g + b   (one block per row of 512)
// ---------------------------------------------------------------------------
__global__ __launch_bounds__(128) void ln_kernel(
    const float* __restrict__ gamma, const float* __restrict__ beta,
    float* __restrict__ out)
{
    __shared__ float sbuf[4];
    const size_t row = blockIdx.x;
    const int tid = threadIdx.x;
    const int lane = tid & 31;
    const int warp = tid >> 5;

    float4 a = ((const float4*)(g_qlin + row * DD))[tid];
    float4 c = ((const float4*)(g_oproj + row * DD))[tid];
    float4 x;
    x.x = a.x + c.x; x.y = a.y + c.y; x.z = a.z + c.z; x.w = a.w + c.w;

    float s = x.x + x.y + x.z + x.w;
    #pragma unroll
    for (int o = 16; o; o >>= 1) s += __shfl_xor_sync(~0u, s, o);
    if (lane == 0) sbuf[warp] = s;
    __syncthreads();
    s = sbuf[0] + sbuf[1] + sbuf[2] + sbuf[3];
    float mu = s * (1.0f / DD);
    __syncthreads();

    float dx = x.x - mu, dy = x.y - mu, dz = x.z - mu, dw = x.w - mu;
    float v = dx * dx + dy * dy + dz * dz + dw * dw;
    #pragma unroll
    for (int o = 16; o; o >>= 1) v += __shfl_xor_sync(~0u, v, o);
    if (lane == 0) sbuf[warp] = v;
    __syncthreads();
    v = sbuf[0] + sbuf[1] + sbuf[2] + sbuf[3];
    float rstd = rsqrtf(v * (1.0f / DD) + EPSLN);

    float4 g4 = ((const float4*)gamma)[tid];
    float4 b4 = ((const float4*)beta)[tid];
    float4 y;
    y.x = dx * rstd * g4.x + b4.x;
    y.y = dy * rstd * g4.y + b4.y;
    y.z = dz * rstd * g4.z + b4.z;
    y.w = dw * rstd * g4.w + b4.w;
    ((float4*)(out + row * DD))[tid] = y;
}

// ---------------------------------------------------------------------------
extern "C" void kernel_launch(void* const* d_in, const int* in_sizes, int n_in,
                              void* d_out, int out_size)
{
    const float* q    = (const float*)d_in[0];
    const float* k    = (const float*)d_in[1];
    const float* v    = (const float*)d_in[2];
    const float* Wq   = (const float*)d_in[3];
    const float* bq   = (const float*)d_in[4];
    const float* Wk   = (const float*)d_in[5];
    const float* bk   = (const float*)d_in[6];
    const float* Wv   = (const float*)d_in[7];
    const float* bv   = (const float*)d_in[8];
    const float* Wo   = (const float*)d_in[9];
    const float* bo   = (const float*)d_in[10];
    const float* ln_g = (const float*)d_in[11];
    const float* ln_b = (const float*)d_in[12];

    float* out  = (float*)d_out;
    float* attn = out + (size_t)LINSZ;   // [B,H,SQ,SK] after [B,SQ,D]

    float *qlin, *klin, *vlin, *ctx, *oproj;
    cudaGetSymbolAddress((void**)&qlin,  g_qlin);
    cudaGetSymbolAddress((void**)&klin,  g_klin);
    cudaGetSymbolAddress((void**)&vlin,  g_vlin);
    cudaGetSymbolAddress((void**)&ctx,   g_ctx);
    cudaGetSymbolAddress((void**)&oproj, g_oproj);

    dim3 blk(256);
    dim3 gl(DD / 128, NTOK / 128);               // (4, 64)

    linear_mma<<<gl, blk>>>(q, Wq, bq, qlin, DD, DD);
    linear_mma<<<gl, blk>>>(k, Wk, bk, klin, DD, DD);
    linear_mma<<<gl, blk>>>(v, Wv, bv, vlin, DD, DD);

    scores_mma<<<dim3(SK_ / 128, SQ / 128, B_ * H_), blk>>>(attn);
    softmax_kernel<<<B_ * H_ * SQ, 256>>>(attn);
    pv_mma<<<dim3(SQ / 128, B_ * H_), blk>>>(attn);

    linear_mma<<<gl, blk>>>(ctx, Wo, bo, oproj, DD, DD);
    ln_kernel<<<NTOK, 128>>>(ln_g, ln_b, out);
}

// round 10
// speedup vs baseline: 2.7295x; 1.0866x over previous
#include <cuda_runtime.h>
#include <cuda_bf16.h>
#include <cstdint>

#define B_  4
#define SQ  2048
#define SK_ 2048
#define DD  512
#define H_  8
#define HD  64
#define SCALE 0.125f
#define EPSLN 1e-5f

#define NTOK (B_*SQ)            // 8192
#define LINSZ (NTOK*DD)         // 4194304

// Scratch (device globals: allocation-free rule)
__device__ float g_qlin[LINSZ];
__device__ float g_ctx[LINSZ];
__device__ float g_oproj[LINSZ];
__device__ __nv_bfloat16 g_qh[LINSZ], g_ql[LINSZ];
__device__ __nv_bfloat16 g_kh[LINSZ], g_kl[LINSZ];
__device__ __nv_bfloat16 g_vh[LINSZ], g_vl[LINSZ];

// ---------------------------------------------------------------------------
// Helpers
// ---------------------------------------------------------------------------
__device__ __forceinline__ void split2(float x, float y, uint32_t& hi, uint32_t& lo) {
    __nv_bfloat16 hx = __float2bfloat16(x), hy = __float2bfloat16(y);
    float rx = x - __bfloat162float(hx);
    float ry = y - __bfloat162float(hy);
    __nv_bfloat16 lx = __float2bfloat16(rx), ly = __float2bfloat16(ry);
    hi = ((uint32_t)__bfloat16_as_ushort(hy) << 16) | __bfloat16_as_ushort(hx);
    lo = ((uint32_t)__bfloat16_as_ushort(ly) << 16) | __bfloat16_as_ushort(lx);
}

__device__ __forceinline__ void mma16816(float* c, const uint32_t* a, const uint32_t* b) {
    asm volatile(
        "mma.sync.aligned.m16n8k16.row.col.f32.bf16.bf16.f32 "
        "{%0,%1,%2,%3},{%4,%5,%6,%7},{%8,%9},{%0,%1,%2,%3};\n"
        : "+f"(c[0]), "+f"(c[1]), "+f"(c[2]), "+f"(c[3])
        : "r"(a[0]), "r"(a[1]), "r"(a[2]), "r"(a[3]), "r"(b[0]), "r"(b[1]));
}

__device__ __forceinline__ uint32_t sh_addr(const void* p) {
    return (uint32_t)__cvta_generic_to_shared(p);
}

__device__ __forceinline__ void ldsm4(uint32_t* r, uint32_t addr) {
    asm volatile("ldmatrix.sync.aligned.m8n8.x4.shared.b16 {%0,%1,%2,%3},[%4];\n"
                 : "=r"(r[0]), "=r"(r[1]), "=r"(r[2]), "=r"(r[3]) : "r"(addr) : "memory");
}

__device__ __forceinline__ void ldsm4t(uint32_t* r, uint32_t addr) {
    asm volatile("ldmatrix.sync.aligned.m8n8.x4.trans.shared.b16 {%0,%1,%2,%3},[%4];\n"
                 : "=r"(r[0]), "=r"(r[1]), "=r"(r[2]), "=r"(r[3]) : "r"(addr) : "memory");
}

// ---------------------------------------------------------------------------
// Linear: Y = X @ W^T + bias. fp32 out optional; split-bf16 hi/lo out optional.
// 128x128 block, 8 warps (2x4), warp tile 64x32, BK=32, split-bf16 3-MMA.
// Stride-36 smem rows: 32-bit LDS only (no ldmatrix) -> alignment OK.
// ---------------------------------------------------------------------------
__global__ __launch_bounds__(256) void linear_mma(
    const float* __restrict__ X, const float* __restrict__ W,
    const float* __restrict__ bias, float* __restrict__ Y,
    __nv_bfloat16* __restrict__ Yh, __nv_bfloat16* __restrict__ Yl,
    int K, int N)
{
    __shared__ __nv_bfloat16 sAh[128 * 36], sAl[128 * 36];
    __shared__ __nv_bfloat16 sBh[128 * 36], sBl[128 * 36];
    const int m0 = blockIdx.y * 128;
    const int n0 = blockIdx.x * 128;
    const float* A  = X + (size_t)m0 * K;
    const float* Bm = W + (size_t)n0 * K;

    const int tid  = threadIdx.x;
    const int wid  = tid >> 5, lane = tid & 31;
    const int wm   = wid >> 2;
    const int wn   = wid & 3;
    const int grp  = lane >> 2;
    const int tig  = lane & 3;

    float acc[4][4][4] = {};

    for (int k0 = 0; k0 < K; k0 += 32) {
        #pragma unroll
        for (int i = 0; i < 4; i++) {
            int s   = tid + i * 256;
            int row = s >> 3;
            int c   = s & 7;
            float4 av = *(const float4*)(A + (size_t)row * K + k0 + c * 4);
            uint32_t h0, l0, h1, l1;
            split2(av.x, av.y, h0, l0);
            split2(av.z, av.w, h1, l1);
            uint32_t* ph = (uint32_t*)(sAh + row * 36 + c * 4);
            uint32_t* pl = (uint32_t*)(sAl + row * 36 + c * 4);
            ph[0] = h0; ph[1] = h1;
            pl[0] = l0; pl[1] = l1;

            float4 bv = *(const float4*)(Bm + (size_t)row * K + k0 + c * 4);
            split2(bv.x, bv.y, h0, l0);
            split2(bv.z, bv.w, h1, l1);
            ph = (uint32_t*)(sBh + row * 36 + c * 4);
            pl = (uint32_t*)(sBl + row * 36 + c * 4);
            ph[0] = h0; ph[1] = h1;
            pl[0] = l0; pl[1] = l1;
        }
        __syncthreads();

        #pragma unroll
        for (int ks = 0; ks < 2; ks++) {
            const int kb = ks * 16 + tig * 2;
            uint32_t ah[4][4], al[4][4];
            #pragma unroll
            for (int i = 0; i < 4; i++) {
                int r0 = wm * 64 + i * 16 + grp;
                ah[i][0] = *(const uint32_t*)(sAh + r0 * 36 + kb);
                ah[i][1] = *(const uint32_t*)(sAh + (r0 + 8) * 36 + kb);
                ah[i][2] = *(const uint32_t*)(sAh + r0 * 36 + kb + 8);
                ah[i][3] = *(const uint32_t*)(sAh + (r0 + 8) * 36 + kb + 8);
                al[i][0] = *(const uint32_t*)(sAl + r0 * 36 + kb);
                al[i][1] = *(const uint32_t*)(sAl + (r0 + 8) * 36 + kb);
                al[i][2] = *(const uint32_t*)(sAl + r0 * 36 + kb + 8);
                al[i][3] = *(const uint32_t*)(sAl + (r0 + 8) * 36 + kb + 8);
            }
            uint32_t bh[4][2], bl[4][2];
            #pragma unroll
            for (int j = 0; j < 4; j++) {
                int nr = wn * 32 + j * 8 + grp;
                bh[j][0] = *(const uint32_t*)(sBh + nr * 36 + kb);
                bh[j][1] = *(const uint32_t*)(sBh + nr * 36 + kb + 8);
                bl[j][0] = *(const uint32_t*)(sBl + nr * 36 + kb);
                bl[j][1] = *(const uint32_t*)(sBl + nr * 36 + kb + 8);
            }
            #pragma unroll
            for (int i = 0; i < 4; i++)
                #pragma unroll
                for (int j = 0; j < 4; j++) {
                    mma16816(acc[i][j], ah[i], bh[j]);
                    mma16816(acc[i][j], ah[i], bl[j]);
                    mma16816(acc[i][j], al[i], bh[j]);
                }
        }
        __syncthreads();
    }

    #pragma unroll
    for (int i = 0; i < 4; i++) {
        #pragma unroll
        for (int j = 0; j < 4; j++) {
            int r  = m0 + wm * 64 + i * 16 + grp;
            int cN = n0 + wn * 32 + j * 8 + tig * 2;
            float bv0 = bias[cN], bv1 = bias[cN + 1];
            float v00 = acc[i][j][0] + bv0, v01 = acc[i][j][1] + bv1;
            float v10 = acc[i][j][2] + bv0, v11 = acc[i][j][3] + bv1;
            size_t o0 = (size_t)r * N + cN;
            size_t o1 = (size_t)(r + 8) * N + cN;
            if (Y) {
                Y[o0] = v00; Y[o0 + 1] = v01;
                Y[o1] = v10; Y[o1 + 1] = v11;
            }
            if (Yh) {
                uint32_t h0, l0, h1, l1;
                split2(v00, v01, h0, l0);
                split2(v10, v11, h1, l1);
                *(uint32_t*)(Yh + o0) = h0; *(uint32_t*)(Yl + o0) = l0;
                *(uint32_t*)(Yh + o1) = h1; *(uint32_t*)(Yl + o1) = l1;
            }
        }
    }
}

// ---------------------------------------------------------------------------
// scores[b,h,q,k] = SCALE * qh . kh   (per bh: M=N=2048, K=64)
// bf16 hi/lo inputs; K staged in two 32-col chunks.
// Stride-40 rows (80 B, 16B-aligned for ldmatrix; conflict-free).
// 8 warps (2x4), warp tile 64x32.
// ---------------------------------------------------------------------------
__global__ __launch_bounds__(256, 2) void scores_mma(
    const __nv_bfloat16* __restrict__ qh, const __nv_bfloat16* __restrict__ ql,
    const __nv_bfloat16* __restrict__ kh, const __nv_bfloat16* __restrict__ kl,
    float* __restrict__ attn)
{
    __shared__ __nv_bfloat16 sQh[128 * 40], sQl[128 * 40];
    __shared__ __nv_bfloat16 sKh[128 * 40], sKl[128 * 40];
    const int tid = threadIdx.x;
    const int wid = tid >> 5, lane = tid & 31;
    const int bh = blockIdx.z, b = bh >> 3, h = bh & 7;
    const int m0 = blockIdx.y * 128, n0 = blockIdx.x * 128;

    const size_t qbase = (size_t)(b * SQ + m0) * DD + h * HD;
    const size_t kbase = (size_t)(b * SK_ + n0) * DD + h * HD;

    const int wm = wid >> 2, wn = wid & 3;
    const int grp = lane >> 2, tig = lane & 3;
    const int lrow = lane & 15, lcol = (lane >> 4) * 8;

    float acc[4][4][4] = {};

    #pragma unroll
    for (int kh0 = 0; kh0 < HD; kh0 += 32) {
        if (kh0) __syncthreads();
        // stage 128 rows x 32 cols of each array (writes <= col 32 <= stride 40)
        #pragma unroll
        for (int i = 0; i < 2; i++) {
            int c = tid + i * 256;          // 0..511 uint4 slots
            int row = c >> 2, off = (c & 3) * 8;
            size_t g = (size_t)row * DD + kh0 + off;
            *(uint4*)&sQh[row * 40 + off] = *(const uint4*)&qh[qbase + g];
            *(uint4*)&sQl[row * 40 + off] = *(const uint4*)&ql[qbase + g];
            *(uint4*)&sKh[row * 40 + off] = *(const uint4*)&kh[kbase + g];
            *(uint4*)&sKl[row * 40 + off] = *(const uint4*)&kl[kbase + g];
        }
        __syncthreads();

        #pragma unroll
        for (int ks = 0; ks < 2; ks++) {
            const int kc = ks * 16 + lcol;      // <= 24, +8 read <= 32
            uint32_t ah[4][4], al[4][4];
            #pragma unroll
            for (int i = 0; i < 4; i++) {
                int r = wm * 64 + i * 16 + lrow;
                ldsm4(ah[i], sh_addr(&sQh[r * 40 + kc]));
                ldsm4(al[i], sh_addr(&sQl[r * 40 + kc]));
            }
            uint32_t bhf[2][4], blf[2][4];
            #pragma unroll
            for (int c = 0; c < 2; c++) {
                int r = wn * 32 + c * 16 + lrow;
                ldsm4(bhf[c], sh_addr(&sKh[r * 40 + kc]));
                ldsm4(blf[c], sh_addr(&sKl[r * 40 + kc]));
            }
            #pragma unroll
            for (int i = 0; i < 4; i++)
                #pragma unroll
                for (int c = 0; c < 2; c++)
                    #pragma unroll
                    for (int hf = 0; hf < 2; hf++) {
                        uint32_t bH[2] = {bhf[c][hf], bhf[c][hf + 2]};
                        uint32_t bL[2] = {blf[c][hf], blf[c][hf + 2]};
                        float* a = acc[i][c * 2 + hf];
                        mma16816(a, ah[i], bH);
                        mma16816(a, ah[i], bL);
                        mma16816(a, al[i], bH);
                    }
        }
    }

    float* obase = attn + (size_t)bh * SQ * SK_ + (size_t)m0 * SK_ + n0;
    #pragma unroll
    for (int i = 0; i < 4; i++)
        #pragma unroll
        for (int j = 0; j < 4; j++) {
            int r  = wm * 64 + i * 16 + grp;
            int cN = wn * 32 + j * 8 + tig * 2;
            float* o0 = obase + (size_t)r * SK_ + cN;
            float* o1 = obase + (size_t)(r + 8) * SK_ + cN;
            o0[0] = acc[i][j][0] * SCALE; o0[1] = acc[i][j][1] * SCALE;
            o1[0] = acc[i][j][2] * SCALE; o1[1] = acc[i][j][3] * SCALE;
        }
}

// ---------------------------------------------------------------------------
// In-place row softmax over SK=2048.
// ---------------------------------------------------------------------------
__global__ __launch_bounds__(256) void softmax_kernel(float* __restrict__ attn)
{
    __shared__ float sbuf[8];
    const size_t row = blockIdx.x;
    float* p = attn + row * (size_t)SK_;
    const int tid = threadIdx.x;
    const int lane = tid & 31;
    const int warp = tid >> 5;

    float4 v0 = ((const float4*)p)[tid];
    float4 v1 = ((const float4*)p)[tid + 256];

    float mx = fmaxf(fmaxf(fmaxf(v0.x, v0.y), fmaxf(v0.z, v0.w)),
                     fmaxf(fmaxf(v1.x, v1.y), fmaxf(v1.z, v1.w)));
    #pragma unroll
    for (int o = 16; o; o >>= 1) mx = fmaxf(mx, __shfl_xor_sync(~0u, mx, o));
    if (lane == 0) sbuf[warp] = mx;
    __syncthreads();
    mx = sbuf[0];
    #pragma unroll
    for (int i = 1; i < 8; i++) mx = fmaxf(mx, sbuf[i]);
    __syncthreads();

    v0.x = expf(v0.x - mx); v0.y = expf(v0.y - mx);
    v0.z = expf(v0.z - mx); v0.w = expf(v0.w - mx);
    v1.x = expf(v1.x - mx); v1.y = expf(v1.y - mx);
    v1.z = expf(v1.z - mx); v1.w = expf(v1.w - mx);

    float s = v0.x + v0.y + v0.z + v0.w + v1.x + v1.y + v1.z + v1.w;
    #pragma unroll
    for (int o = 16; o; o >>= 1) s += __shfl_xor_sync(~0u, s, o);
    if (lane == 0) sbuf[warp] = s;
    __syncthreads();
    s = sbuf[0];
    #pragma unroll
    for (int i = 1; i < 8; i++) s += sbuf[i];

    float inv = 1.0f / s;
    v0.x *= inv; v0.y *= inv; v0.z *= inv; v0.w *= inv;
    v1.x *= inv; v1.y *= inv; v1.z *= inv; v1.w *= inv;
    ((float4*)p)[tid] = v0;
    ((float4*)p)[tid + 256] = v1;
}

// ---------------------------------------------------------------------------
// ctx = P @ V  (per bh: M=2048, N=64, K=2048), BK=32.
// P fp32 split in-kernel (stride-40 rows, 16B-aligned for ldmatrix);
// V bf16 hi/lo staged [32k][64n] (stride-72 elem = 144 B, 16B-aligned),
// trans-ldmatrix. 8 warps = 4m x 2n, warp tile 32x32.
// ---------------------------------------------------------------------------
__global__ __launch_bounds__(256, 2) void pv_mma(
    const float* __restrict__ attn,
    const __nv_bfloat16* __restrict__ vh, const __nv_bfloat16* __restrict__ vl,
    float* __restrict__ ctx)
{
    __shared__ __nv_bfloat16 sPh[128 * 40], sPl[128 * 40];
    __shared__ __nv_bfloat16 sVh[32 * 72],  sVl[32 * 72];
    const int tid = threadIdx.x;
    const int wid = tid >> 5, lane = tid & 31;
    const int wm = wid >> 1, wn = wid & 1;
    const int grp = lane >> 2, tig = lane & 3;
    const int lrow = lane & 15, lcol = (lane >> 4) * 8;
    const int bh = blockIdx.y, b = bh >> 3, h = bh & 7;
    const int m0 = blockIdx.x * 128;

    const float* P = attn + (size_t)bh * SQ * SK_ + (size_t)m0 * SK_;
    const size_t vbase = (size_t)b * SK_ * DD + h * HD;

    float acc[2][4][4] = {};

    for (int k0 = 0; k0 < SK_; k0 += 32) {
        // stage P: 128 x 32 fp32 -> hi/lo bf16 (writes <= col 32 <= stride 40)
        #pragma unroll
        for (int i = 0; i < 4; i++) {
            int c = tid + i * 256;          // 0..1023 float4 chunks
            int row = c >> 3, off = (c & 7) * 4;
            float4 pv = *(const float4*)(P + (size_t)row * SK_ + k0 + off);
            uint32_t h0, l0, h1, l1;
            split2(pv.x, pv.y, h0, l0);
            split2(pv.z, pv.w, h1, l1);
            uint32_t* ph = (uint32_t*)(sPh + row * 40 + off);
            uint32_t* pl = (uint32_t*)(sPl + row * 40 + off);
            ph[0] = h0; ph[1] = h1;
            pl[0] = l0; pl[1] = l1;
        }
        // stage V: 32(k) x 64(n) bf16 rows (stride 72 elem = 144 B)
        {
            int row = tid >> 3, off = (tid & 7) * 8;    // 0..31, 0..56
            size_t g = vbase + (size_t)(k0 + row) * DD + off;
            *(uint4*)&sVh[row * 72 + off] = *(const uint4*)&vh[g];
            *(uint4*)&sVl[row * 72 + off] = *(const uint4*)&vl[g];
        }
        __syncthreads();

        #pragma unroll
        for (int ks = 0; ks < 2; ks++) {
            const int kc = ks * 16 + lcol;
            uint32_t ah[2][4], al[2][4];
            #pragma unroll
            for (int i = 0; i < 2; i++) {
                int r = wm * 32 + i * 16 + lrow;
                ldsm4(ah[i], sh_addr(&sPh[r * 40 + kc]));
                ldsm4(al[i], sh_addr(&sPl[r * 40 + kc]));
            }
            uint32_t bhf[2][4], blf[2][4];
            #pragma unroll
            for (int c = 0; c < 2; c++) {
                int kr = ks * 16 + lrow;                // 0..31
                int nc = wn * 32 + c * 16 + lcol;       // <= 56, +8 read <= 64
                ldsm4t(bhf[c], sh_addr(&sVh[kr * 72 + nc]));
                ldsm4t(blf[c], sh_addr(&sVl[kr * 72 + nc]));
            }
            #pragma unroll
            for (int i = 0; i < 2; i++)
                #pragma unroll
                for (int c = 0; c < 2; c++)
                    #pragma unroll
                    for (int hf = 0; hf < 2; hf++) {
                        uint32_t bH[2] = {bhf[c][hf * 2], bhf[c][hf * 2 + 1]};
                        uint32_t bL[2] = {blf[c][hf * 2], blf[c][hf * 2 + 1]};
                        float* a = acc[i][c * 2 + hf];
                        mma16816(a, ah[i], bH);
                        mma16816(a, ah[i], bL);
                        mma16816(a, al[i], bH);
                    }
        }
        __syncthreads();
    }

    #pragma unroll
    for (int i = 0; i < 2; i++)
        #pragma unroll
        for (int j = 0; j < 4; j++) {
            int r  = m0 + wm * 32 + i * 16 + grp;
            int cN = wn * 32 + j * 8 + tig * 2;
            float* o0 = ctx + (size_t)(b * SQ + r) * DD + h * HD + cN;
            float* o1 = ctx + (size_t)(b * SQ + r + 8) * DD + h * HD + cN;
            o0[0] = acc[i][j][0]; o0[1] = acc[i][j][1];
            o1[0] = acc[i][j][2]; o1[1] = acc[i][j][3];
        }
}

// ---------------------------------------------------------------------------
// out = LayerNorm(q_lin + oproj) * g + b
// ---------------------------------------------------------------------------
__global__ __launch_bounds__(128) void ln_kernel(
    const float* __restrict__ gamma, const float* __restrict__ beta,
    float* __restrict__ out)
{
    __shared__ float sbuf[4];
    const size_t row = blockIdx.x;
    const int tid = threadIdx.x;
    const int lane = tid & 31;
    const int warp = tid >> 5;

    float4 a = ((const float4*)(g_qlin + row * DD))[tid];
    float4 c = ((const float4*)(g_oproj + row * DD))[tid];
    float4 x;
    x.x = a.x + c.x; x.y = a.y + c.y; x.z = a.z + c.z; x.w = a.w + c.w;

    float s = x.x + x.y + x.z + x.w;
    #pragma unroll
    for (int o = 16; o; o >>= 1) s += __shfl_xor_sync(~0u, s, o);
    if (lane == 0) sbuf[warp] = s;
    __syncthreads();
    s = sbuf[0] + sbuf[1] + sbuf[2] + sbuf[3];
    float mu = s * (1.0f / DD);
    __syncthreads();

    float dx = x.x - mu, dy = x.y - mu, dz = x.z - mu, dw = x.w - mu;
    float v = dx * dx + dy * dy + dz * dz + dw * dw;
    #pragma unroll
    for (int o = 16; o; o >>= 1) v += __shfl_xor_sync(~0u, v, o);
    if (lane == 0) sbuf[warp] = v;
    __syncthreads();
    v = sbuf[0] + sbuf[1] + sbuf[2] + sbuf[3];
    float rstd = rsqrtf(v * (1.0f / DD) + EPSLN);

    float4 g4 = ((const float4*)gamma)[tid];
    float4 b4 = ((const float4*)beta)[tid];
    float4 y;
    y.x = dx * rstd * g4.x + b4.x;
    y.y = dy * rstd * g4.y + b4.y;
    y.z = dz * rstd * g4.z + b4.z;
    y.w = dw * rstd * g4.w + b4.w;
    ((float4*)(out + row * DD))[tid] = y;
}

// ---------------------------------------------------------------------------
extern "C" void kernel_launch(void* const* d_in, const int* in_sizes, int n_in,
                              void* d_out, int out_size)
{
    const float* q    = (const float*)d_in[0];
    const float* k    = (const float*)d_in[1];
    const float* v    = (const float*)d_in[2];
    const float* Wq   = (const float*)d_in[3];
    const float* bq   = (const float*)d_in[4];
    const float* Wk   = (const float*)d_in[5];
    const float* bk   = (const float*)d_in[6];
    const float* Wv   = (const float*)d_in[7];
    const float* bv   = (const float*)d_in[8];
    const float* Wo   = (const float*)d_in[9];
    const float* bo   = (const float*)d_in[10];
    const float* ln_g = (const float*)d_in[11];
    const float* ln_b = (const float*)d_in[12];

    float* out  = (float*)d_out;
    float* attn = out + (size_t)LINSZ;

    float *qlin, *ctx, *oproj;
    __nv_bfloat16 *qh, *ql, *kh, *kl, *vh, *vl;
    cudaGetSymbolAddress((void**)&qlin,  g_qlin);
    cudaGetSymbolAddress((void**)&ctx,   g_ctx);
    cudaGetSymbolAddress((void**)&oproj, g_oproj);
    cudaGetSymbolAddress((void**)&qh, g_qh);
    cudaGetSymbolAddress((void**)&ql, g_ql);
    cudaGetSymbolAddress((void**)&kh, g_kh);
    cudaGetSymbolAddress((void**)&kl, g_kl);
    cudaGetSymbolAddress((void**)&vh, g_vh);
    cudaGetSymbolAddress((void**)&vl, g_vl);

    dim3 blk(256);
    dim3 gl(DD / 128, NTOK / 128);               // (4, 64)

    linear_mma<<<gl, blk>>>(q, Wq, bq, qlin, qh, ql, DD, DD);
    linear_mma<<<gl, blk>>>(k, Wk, bk, nullptr, kh, kl, DD, DD);
    linear_mma<<<gl, blk>>>(v, Wv, bv, nullptr, vh, vl, DD, DD);

    scores_mma<<<dim3(SK_ / 128, SQ / 128, B_ * H_), blk>>>(qh, ql, kh, kl, attn);
    softmax_kernel<<<B_ * H_ * SQ, 256>>>(attn);
    pv_mma<<<dim3(SQ / 128, B_ * H_), blk>>>(attn, vh, vl, ctx);

    linear_mma<<<gl, blk>>>(ctx, Wo, bo, oproj, nullptr, nullptr, DD, DD);
    ln_kernel<<<NTOK, 128>>>(ln_g, ln_b, out);
}